// round 13
// baseline (speedup 1.0000x reference)
#include <cuda_runtime.h>
#include <cuda_bf16.h>
#include <math.h>
#include <stdint.h>

#define BATCH 4
#define SEQ 1024
#define DIM 256
#define NH 8
#define DH 32
#define ROWS (BATCH*SEQ)      // 4096
#define MAXN 256
#define FFH 512
#define HD2 (NH*DIM)          // 2048

// ---------------- scratch ---------------------------------------------------------
__device__ float g_hp [ROWS*DIM];
__device__ float g_h  [ROWS*DIM];
__device__ float g_ln [ROWS*DIM];
__device__ float g_part[4*ROWS*DIM];        // split-K partials (16 MB)
__device__ __nv_bfloat16 gA_hi[ROWS*HD2];
__device__ __nv_bfloat16 gA_lo[ROWS*HD2];
__device__ __nv_bfloat16 gF_hi[ROWS*FFH];
__device__ __nv_bfloat16 gF_lo[ROWS*FFH];
__device__ __nv_bfloat16 w0_hi[DIM*DIM],  w0_lo[DIM*DIM];
__device__ __nv_bfloat16 w1_hi[DIM*DIM],  w1_lo[DIM*DIM];
__device__ __nv_bfloat16 w2_hi[DIM*HD2],  w2_lo[DIM*HD2];
__device__ __nv_bfloat16 f1_hi[FFH*DIM],  f1_lo[FFH*DIM];
__device__ __nv_bfloat16 f2_hi[DIM*FFH],  f2_lo[DIM*FFH];
__device__ float g_va_src[NH*DIM];
__device__ float g_va_dst[NH*DIM];
__device__ float g_src [ROWS*NH];
__device__ float g_dst [ROWS*NH];
__device__ float g_src2[ROWS*NH];
__device__ float g_dst2[ROWS*NH];
__device__ int   g_nbr[ROWS*MAXN];
__device__ int   g_cnt[ROWS];

// ---------------- helpers ---------------------------------------------------------
__device__ __forceinline__ uint32_t smem_u32(const void* p){
    uint32_t a;
    asm("{ .reg .u64 t; cvta.to.shared.u64 t, %1; cvt.u32.u64 %0, t; }" : "=r"(a) : "l"(p));
    return a;
}
__device__ __forceinline__ void split_val(float v, __nv_bfloat16& hi, __nv_bfloat16& lo){
    hi = __float2bfloat16(v);
    lo = __float2bfloat16(v - __bfloat162float(hi));
}
__device__ __forceinline__ uint64_t pack2(float x, float y){
    uint64_t p;
    asm("mov.b64 %0, {%1,%2};" : "=l"(p) : "f"(x), "f"(y));
    return p;
}
__device__ __forceinline__ void unpack2(uint64_t p, float& x, float& y){
    asm("mov.b64 {%0,%1}, %2;" : "=f"(x), "=f"(y) : "l"(p));
}
__device__ __forceinline__ void ffma2(uint64_t& d, uint64_t a, uint64_t b){
    asm("fma.rn.f32x2 %0, %1, %2, %0;" : "+l"(d) : "l"(a), "l"(b));
}
#define CPA16(dst, src) \
    asm volatile("cp.async.cg.shared.global [%0], [%1], 16;" :: "r"(dst), "l"(src) : "memory")
#define LDSM4(r0,r1,r2,r3,addr) \
    asm volatile("ldmatrix.sync.aligned.m8n8.x4.shared.b16 {%0,%1,%2,%3}, [%4];" \
        : "=r"(r0),"=r"(r1),"=r"(r2),"=r"(r3) : "r"(addr))

__device__ __forceinline__ void mma_bf16(float* c, const uint32_t* a, uint32_t b0, uint32_t b1){
    asm volatile("mma.sync.aligned.m16n8k16.row.col.f32.bf16.bf16.f32 "
        "{%0,%1,%2,%3}, {%4,%5,%6,%7}, {%8,%9}, {%0,%1,%2,%3};"
        : "+f"(c[0]),"+f"(c[1]),"+f"(c[2]),"+f"(c[3])
        : "r"(a[0]),"r"(a[1]),"r"(a[2]),"r"(a[3]), "r"(b0),"r"(b1));
}

// ---------------- HMMA split-bf16 GEMM, TM=128, 3-stage pipeline ------------------
// EPI: 0 plain (z-offset partial); 1 +bias GELU -> bf16 split; 2 +bias+res; 4 plain + fused scores
template<int EPI, int TN>
__global__ __launch_bounds__(256)
void gemm_mma(const __nv_bfloat16* __restrict__ Ah, const __nv_bfloat16* __restrict__ Al,
              const __nv_bfloat16* __restrict__ Bh, const __nv_bfloat16* __restrict__ Bl,
              const float* __restrict__ bias, const float* __restrict__ res,
              const float* __restrict__ asv, const float* __restrict__ adv,
              float* __restrict__ C, __nv_bfloat16* __restrict__ Chi, __nv_bfloat16* __restrict__ Clo,
              int M, int N, int K, int Kloop){
    constexpr int LD   = 40;
    constexpr int A_SZ = 128*LD*2;
    constexpr int B_SZ = TN*LD*2;
    constexpr int BUF  = 2*A_SZ + 2*B_SZ;
    constexpr int NB   = TN/16;
    constexpr int NP   = TN/32;
    extern __shared__ char sm[];
    uint32_t sb = smem_u32(sm);
    int tid = threadIdx.x, lane = tid & 31, wid = tid >> 5;
    int bm = blockIdx.y*128, bn = blockIdx.x*TN;
    int wm = (wid & 3)*32, wn = (wid >> 2)*(TN/2);
    int koff = blockIdx.z * Kloop;
    float acc[2][NB][4] = {};
    int nch = Kloop >> 5;

    auto load_chunk = [&](int c){
        uint32_t s0 = sb + (c % 3)*BUF;
        int k0 = koff + c*32;
        #pragma unroll
        for (int i = 0; i < 2; i++){
            int u = tid + i*256;
            int row = u >> 2, c8 = u & 3;
            uint32_t so = (uint32_t)(row*LD + c8*8)*2;
            size_t go = (size_t)(bm + row)*K + k0 + c8*8;
            CPA16(s0 + so,        Ah + go);
            CPA16(s0 + A_SZ + so, Al + go);
        }
        for (int u = tid; u < TN*4; u += 256){
            int row = u >> 2, c8 = u & 3;
            uint32_t so = (uint32_t)(row*LD + c8*8)*2;
            size_t go = (size_t)(bn + row)*K + k0 + c8*8;
            CPA16(s0 + 2*A_SZ + so,        Bh + go);
            CPA16(s0 + 2*A_SZ + B_SZ + so, Bl + go);
        }
        asm volatile("cp.async.commit_group;" ::: "memory");
    };

    load_chunk(0);
    load_chunk(1);
    for (int c = 0; c < nch; c++){
        if (c + 2 < nch){
            load_chunk(c + 2);
            asm volatile("cp.async.wait_group 2;" ::: "memory");
        } else if (c + 1 < nch){
            asm volatile("cp.async.wait_group 1;" ::: "memory");
        } else {
            asm volatile("cp.async.wait_group 0;" ::: "memory");
        }
        __syncthreads();
        uint32_t sA = sb + (c % 3)*BUF;
        uint32_t sB = sA + 2*A_SZ;
        #pragma unroll
        for (int kk = 0; kk < 32; kk += 16){
            uint32_t ah[2][4], al[2][4];
            #pragma unroll
            for (int mb = 0; mb < 2; mb++){
                uint32_t ad = sA + (uint32_t)(((wm + mb*16 + (lane & 15))*LD + kk + (lane >> 4)*8)*2);
                LDSM4(ah[mb][0],ah[mb][1],ah[mb][2],ah[mb][3], ad);
                LDSM4(al[mb][0],al[mb][1],al[mb][2],al[mb][3], ad + A_SZ);
            }
            #pragma unroll
            for (int p = 0; p < NP; p++){
                uint32_t bd = sB + (uint32_t)(((wn + p*16 + ((lane >> 4) << 3) + (lane & 7))*LD
                                              + kk + ((lane >> 3) & 1)*8)*2);
                uint32_t bh[4], bl[4];
                LDSM4(bh[0],bh[1],bh[2],bh[3], bd);
                LDSM4(bl[0],bl[1],bl[2],bl[3], bd + B_SZ);
                #pragma unroll
                for (int j = 0; j < 2; j++){
                    #pragma unroll
                    for (int mb = 0; mb < 2; mb++){
                        float* a_ = acc[mb][p*2 + j];
                        mma_bf16(a_, ah[mb], bh[2*j], bh[2*j+1]);
                        mma_bf16(a_, ah[mb], bl[2*j], bl[2*j+1]);
                        mma_bf16(a_, al[mb], bh[2*j], bh[2*j+1]);
                    }
                }
            }
        }
        __syncthreads();
    }

    int g = lane >> 2, tg = lane & 3;
    float ca[8], cd[8];
    float sacc[2][2] = {}, dacc[2][2] = {};
    int hidx = 0;
    if (EPI == 4){
        hidx = (bn + wn) >> 5;
        #pragma unroll
        for (int nb = 0; nb < 4; nb++)
            #pragma unroll
            for (int e = 0; e < 2; e++){
                int chi = nb*8 + tg*2 + e;
                ca[nb*2+e] = asv[hidx*DH + chi];
                cd[nb*2+e] = adv[hidx*DH + chi];
            }
    }
    size_t zoff = (EPI == 0) ? (size_t)blockIdx.z * M * N : 0;
    #pragma unroll
    for (int mb = 0; mb < 2; mb++){
        #pragma unroll
        for (int nb = 0; nb < NB; nb++){
            float* a_ = acc[mb][nb];
            int col = bn + wn + nb*8 + tg*2;
            #pragma unroll
            for (int half = 0; half < 2; half++){
                int r = bm + wm + mb*16 + g + half*8;
                size_t ci = (size_t)r*N + col;
                float v0 = a_[half*2], v1 = a_[half*2+1];
                if (EPI == 0){
                    *(float2*)&C[zoff + ci] = make_float2(v0, v1);
                } else if (EPI == 4){
                    *(float2*)&C[ci] = make_float2(v0, v1);
                    sacc[mb][half] = fmaf(v0, ca[nb*2], fmaf(v1, ca[nb*2+1], sacc[mb][half]));
                    dacc[mb][half] = fmaf(v0, cd[nb*2], fmaf(v1, cd[nb*2+1], dacc[mb][half]));
                } else if (EPI == 1){
                    v0 += bias[col]; v1 += bias[col+1];
                    float t0 = 0.7978845608028654f*(v0 + 0.044715f*v0*v0*v0);
                    v0 = 0.5f*v0*(1.f + tanhf(t0));
                    float t1 = 0.7978845608028654f*(v1 + 0.044715f*v1*v1*v1);
                    v1 = 0.5f*v1*(1.f + tanhf(t1));
                    __nv_bfloat16 h0,l0,h1,l1;
                    split_val(v0,h0,l0); split_val(v1,h1,l1);
                    __nv_bfloat162 hp2; hp2.x=h0; hp2.y=h1;
                    __nv_bfloat162 lp2; lp2.x=l0; lp2.y=l1;
                    *(__nv_bfloat162*)&Chi[ci] = hp2;
                    *(__nv_bfloat162*)&Clo[ci] = lp2;
                } else if (EPI == 2){
                    float2 rr = *(const float2*)&res[ci];
                    *(float2*)&C[ci] = make_float2(v0 + bias[col] + rr.x, v1 + bias[col+1] + rr.y);
                }
            }
        }
    }
    if (EPI == 4){
        #pragma unroll
        for (int mb = 0; mb < 2; mb++)
            #pragma unroll
            for (int half = 0; half < 2; half++){
                float s = sacc[mb][half], d = dacc[mb][half];
                s += __shfl_xor_sync(0xffffffffu, s, 1);
                s += __shfl_xor_sync(0xffffffffu, s, 2);
                d += __shfl_xor_sync(0xffffffffu, d, 1);
                d += __shfl_xor_sync(0xffffffffu, d, 2);
                if (tg == 0){
                    int r = bm + wm + mb*16 + g + half*8;
                    g_src[r*NH + hidx] = s;
                    g_dst[r*NH + hidx] = d;
                }
            }
    }
}

// ---------------- merged prep ----------------------------------------------------
__device__ __forceinline__ void trans_tile(const float* __restrict__ inp, int ldi,
                                           __nv_bfloat16* __restrict__ oh, __nv_bfloat16* __restrict__ ol,
                                           int ldo, int kt, int nt, float scale){
    __shared__ float tile[32][33];
    int tx = threadIdx.x & 31, ty0 = threadIdx.x >> 5;
    #pragma unroll
    for (int i = 0; i < 4; i++){
        int ty = ty0 + i*8;
        tile[ty][tx] = inp[(size_t)(kt*32 + ty)*ldi + nt*32 + tx];
    }
    __syncthreads();
    #pragma unroll
    for (int i = 0; i < 4; i++){
        int ty = ty0 + i*8;
        float v = scale * tile[tx][ty];
        size_t oi = (size_t)(nt*32 + ty)*ldo + kt*32 + tx;
        __nv_bfloat16 hi, lo; split_val(v, hi, lo);
        oh[oi] = hi; ol[oi] = lo;
    }
}

__global__ __launch_bounds__(256)
void prep(const float* __restrict__ W0, const float* __restrict__ W1, const float* __restrict__ W2,
          const float* __restrict__ F1, const float* __restrict__ F2,
          const float* __restrict__ x,
          const float* __restrict__ as2, const float* __restrict__ ad2,
          const float* __restrict__ adj){
    int b = blockIdx.x, tid = threadIdx.x;
    if (b < 64){
        trans_tile(W0, DIM, w0_hi, w0_lo, DIM, b >> 3, b & 7, 1.f);
    } else if (b < 128){
        int t = b - 64;
        trans_tile(W1, DIM, w1_hi, w1_lo, DIM, t >> 3, t & 7, 1.f);
    } else if (b < 640){
        int rel = b - 128, h = rel >> 6, t = rel & 63;
        trans_tile(W2 + h*DIM, HD2, w2_hi + h*DIM, w2_lo + h*DIM, HD2, t >> 3, t & 7, 0.125f);
    } else if (b < 768){
        int rel = b - 640;
        trans_tile(F1, FFH, f1_hi, f1_lo, DIM, rel >> 4, rel & 15, 1.f);
    } else if (b < 896){
        int rel = b - 768;
        trans_tile(F2, DIM, f2_hi, f2_lo, FFH, rel >> 3, rel & 7, 1.f);
    } else if (b < 1920){
        int idx4 = (b - 896)*256 + tid;
        float4 v = *(const float4*)&x[idx4*4];
        __nv_bfloat16 h0,l0,h1,l1,h2,l2,h3,l3;
        split_val(v.x,h0,l0); split_val(v.y,h1,l1);
        split_val(v.z,h2,l2); split_val(v.w,h3,l3);
        __nv_bfloat162 ha; ha.x=h0; ha.y=h1;
        __nv_bfloat162 hb; hb.x=h2; hb.y=h3;
        __nv_bfloat162 la; la.x=l0; la.y=l1;
        __nv_bfloat162 lb; lb.x=l2; lb.y=l3;
        *(__nv_bfloat162*)&gA_hi[idx4*4]   = ha;
        *(__nv_bfloat162*)&gA_hi[idx4*4+2] = hb;
        *(__nv_bfloat162*)&gA_lo[idx4*4]   = la;
        *(__nv_bfloat162*)&gA_lo[idx4*4+2] = lb;
    } else if (b < 2176){
        int rel = b - 1920;
        int gw = rel*8 + (tid >> 5);
        int lane = tid & 31;
        int h = gw >> 8, c = gw & 255;
        float s = 0.f, t = 0.f;
        #pragma unroll
        for (int d = lane; d < DIM; d += 32){
            float wv = W2[(size_t)c*HD2 + h*DIM + d];
            s += wv * as2[h*DIM + d];
            t += wv * ad2[h*DIM + d];
        }
        #pragma unroll
        for (int o = 16; o > 0; o >>= 1){
            s += __shfl_down_sync(0xffffffffu, s, o);
            t += __shfl_down_sync(0xffffffffu, t, o);
        }
        if (lane == 0){ g_va_src[h*DIM + c] = s; g_va_dst[h*DIM + c] = t; }
    } else {
        // adj scan: warp per row, float4 loads (neighbor order interleaved but deterministic)
        int row = (b - 2176)*8 + (tid >> 5);
        int lane = tid & 31;
        const float* arow = adj + (size_t)row * SEQ;
        int cnt = 0;
        for (int base = 0; base < SEQ; base += 128){
            float4 v = *(const float4*)&arow[base + lane*4];
            float vv[4] = {v.x, v.y, v.z, v.w};
            #pragma unroll
            for (int i = 0; i < 4; i++){
                bool p = vv[i] > 0.f;
                unsigned m = __ballot_sync(0xffffffffu, p);
                if (p){
                    int pos = cnt + __popc(m & ((1u << lane) - 1u));
                    if (pos < MAXN) g_nbr[row*MAXN + pos] = base + lane*4 + i;
                }
                cnt += __popc(m);
            }
        }
        if (lane == 0) g_cnt[row] = cnt < MAXN ? cnt : MAXN;
    }
}

// ---------------- softmax weights -------------------------------------------------
__device__ __forceinline__ void compute_weights(int row, int b, int cnt,
                                                const int* nbr, float* w, float* srcI,
                                                const float* __restrict__ srcA,
                                                const float* __restrict__ dstA){
    int tid = threadIdx.x;
    if (tid < NH) srcI[tid] = srcA[row*NH + tid];
    __syncthreads();
    for (int idx = tid; idx < cnt*NH; idx += 256){
        int n = idx >> 3, h = idx & 7;
        float e = srcI[h] + dstA[(size_t)(b*SEQ + nbr[n])*NH + h];
        w[n*NH + h] = e > 0.f ? e : 0.2f*e;
    }
    __syncthreads();
    int h = tid >> 5, lane = tid & 31;
    float m = -1e30f;
    for (int n = lane; n < cnt; n += 32) m = fmaxf(m, w[n*NH + h]);
    #pragma unroll
    for (int o = 16; o > 0; o >>= 1) m = fmaxf(m, __shfl_xor_sync(0xffffffffu, m, o));
    float ssum = 0.f;
    for (int n = lane; n < cnt; n += 32){
        float e = expf(w[n*NH + h] - m);
        w[n*NH + h] = e;
        ssum += e;
    }
    #pragma unroll
    for (int o = 16; o > 0; o >>= 1) ssum += __shfl_xor_sync(0xffffffffu, ssum, o);
    float inv = 1.f / ssum;
    for (int n = lane; n < cnt; n += 32) w[n*NH + h] *= inv;
    __syncthreads();
}

// aggregate (float4, 4-group) + residual + ELU (+optionally fused layer-2 scores)
template<bool S2>
__global__ __launch_bounds__(256)
void attn01(const float* __restrict__ resid, float* __restrict__ out){
    int row = blockIdx.x;
    int b = row / SEQ;
    int tid = threadIdx.x;
    int cnt = g_cnt[row];
    __shared__ int   nbr[MAXN];
    __shared__ float w[MAXN*NH];
    __shared__ float srcI[NH];
    __shared__ float sred[4][DIM];
    __shared__ float val[DIM];
    for (int n = tid; n < cnt; n += 256) nbr[n] = g_nbr[row*MAXN + n];
    __syncthreads();
    compute_weights(row, b, cnt, nbr, w, srcI, g_src, g_dst);

    int g4 = tid >> 6, c4 = tid & 63;
    int ch0 = c4*4;
    int hh = c4 >> 3;
    float a0 = 0.f, a1 = 0.f, a2 = 0.f, a3 = 0.f;
    float b0_ = 0.f, b1_ = 0.f, b2_ = 0.f, b3_ = 0.f;
    int n = g4;
    for (; n + 4 < cnt; n += 8){
        int j0 = nbr[n], j1 = nbr[n+4];
        float4 v0 = *(const float4*)&g_hp[((size_t)(b*SEQ + j0))*DIM + ch0];
        float4 v1 = *(const float4*)&g_hp[((size_t)(b*SEQ + j1))*DIM + ch0];
        float wt0 = w[n*NH + hh];
        float wt1 = w[(n+4)*NH + hh];
        a0 = fmaf(wt0, v0.x, a0); a1 = fmaf(wt0, v0.y, a1);
        a2 = fmaf(wt0, v0.z, a2); a3 = fmaf(wt0, v0.w, a3);
        b0_ = fmaf(wt1, v1.x, b0_); b1_ = fmaf(wt1, v1.y, b1_);
        b2_ = fmaf(wt1, v1.z, b2_); b3_ = fmaf(wt1, v1.w, b3_);
    }
    if (n < cnt){
        int j0 = nbr[n];
        float4 v0 = *(const float4*)&g_hp[((size_t)(b*SEQ + j0))*DIM + ch0];
        float wt0 = w[n*NH + hh];
        a0 = fmaf(wt0, v0.x, a0); a1 = fmaf(wt0, v0.y, a1);
        a2 = fmaf(wt0, v0.z, a2); a3 = fmaf(wt0, v0.w, a3);
    }
    a0 += b0_; a1 += b1_; a2 += b2_; a3 += b3_;
    *(float4*)&sred[g4][ch0] = make_float4(a0, a1, a2, a3);
    __syncthreads();

    int ch = tid;
    float acc = sred[0][ch] + sred[1][ch] + sred[2][ch] + sred[3][ch];
    size_t oi = (size_t)row*DIM + ch;
    float v = acc + resid[oi];
    v = v > 0.f ? v : expm1f(v);
    out[oi] = v;
    if (!S2){
        split_val(v, gA_hi[oi], gA_lo[oi]);
    } else {
        val[ch] = v;
        __syncthreads();
        int h = tid >> 5, lane = tid & 31;
        float s = 0.f, t = 0.f;
        #pragma unroll
        for (int d = lane; d < DIM; d += 32){
            float vd = val[d];
            s = fmaf(vd, g_va_src[h*DIM + d], s);
            t = fmaf(vd, g_va_dst[h*DIM + d], t);
        }
        #pragma unroll
        for (int o = 16; o > 0; o >>= 1){
            s += __shfl_down_sync(0xffffffffu, s, o);
            t += __shfl_down_sync(0xffffffffu, t, o);
        }
        if (lane == 0){ g_src2[row*NH + h] = s; g_dst2[row*NH + h] = t; }
    }
}

// layer 2: aggregate h per head — 4-group float4 gather + FFMA2 packed math
__global__ __launch_bounds__(256)
void attn2b(){
    int row = blockIdx.x;
    int b = row / SEQ;
    int tid = threadIdx.x;
    int cnt = g_cnt[row];
    __shared__ int   nbr[MAXN];
    __shared__ float w[MAXN*NH];
    __shared__ float srcI[NH];
    __shared__ float sred[4][NH][DIM];   // 32 KB
    for (int n = tid; n < cnt; n += 256) nbr[n] = g_nbr[row*MAXN + n];
    __syncthreads();
    compute_weights(row, b, cnt, nbr, w, srcI, g_src2, g_dst2);

    int g4 = tid >> 6, c4 = tid & 63;
    int ch0 = c4*4;
    uint64_t acc2[NH][2] = {};           // 8 heads x (ch0/1, ch2/3) packed f32x2
    for (int n = g4; n < cnt; n += 4){
        int j = nbr[n];
        float4 v = *(const float4*)&g_h[(size_t)(b*SEQ + j)*DIM + ch0];
        uint64_t v01 = pack2(v.x, v.y);
        uint64_t v23 = pack2(v.z, v.w);
        float4 wa = *(const float4*)&w[n*NH];
        float4 wb = *(const float4*)&w[n*NH + 4];
        float ws[8] = {wa.x, wa.y, wa.z, wa.w, wb.x, wb.y, wb.z, wb.w};
        #pragma unroll
        for (int h = 0; h < NH; h++){
            uint64_t wp = pack2(ws[h], ws[h]);
            ffma2(acc2[h][0], v01, wp);
            ffma2(acc2[h][1], v23, wp);
        }
    }
    #pragma unroll
    for (int h = 0; h < NH; h++){
        float f0, f1, f2, f3;
        unpack2(acc2[h][0], f0, f1);
        unpack2(acc2[h][1], f2, f3);
        *(float4*)&sred[g4][h][ch0] = make_float4(f0, f1, f2, f3);
    }
    __syncthreads();

    int c = tid;
    #pragma unroll
    for (int h = 0; h < NH; h++){
        float s = sred[0][h][c] + sred[1][h][c] + sred[2][h][c] + sred[3][h][c];
        size_t oi = (size_t)row*HD2 + h*DIM + c;
        split_val(s, gA_hi[oi], gA_lo[oi]);
    }
}

// ---------------- LayerNorm over sum of 4 split-K partials + residual -------------
__global__ void layernorm4(const float* __restrict__ res,
                           const float* __restrict__ ln_g, const float* __restrict__ ln_b,
                           float* __restrict__ out){
    int row = blockIdx.x, tid = threadIdx.x;
    size_t oi = (size_t)row*DIM + tid;
    float v = g_part[oi] + g_part[oi + (size_t)ROWS*DIM]
            + g_part[oi + 2*(size_t)ROWS*DIM] + g_part[oi + 3*(size_t)ROWS*DIM]
            + res[oi];
    __shared__ float red[8];
    __shared__ float mu, rstd;
    float s = v;
    #pragma unroll
    for (int o = 16; o > 0; o >>= 1) s += __shfl_xor_sync(0xffffffffu, s, o);
    if ((tid & 31) == 0) red[tid >> 5] = s;
    __syncthreads();
    if (tid == 0){ float t = 0.f; for (int i = 0; i < 8; i++) t += red[i]; mu = t / 256.f; }
    __syncthreads();
    float d = v - mu;
    s = d*d;
    #pragma unroll
    for (int o = 16; o > 0; o >>= 1) s += __shfl_xor_sync(0xffffffffu, s, o);
    if ((tid & 31) == 0) red[tid >> 5] = s;
    __syncthreads();
    if (tid == 0){ float t = 0.f; for (int i = 0; i < 8; i++) t += red[i]; rstd = rsqrtf(t/256.f + 1e-5f); }
    __syncthreads();
    float o = d*rstd*ln_g[tid] + ln_b[tid];
    out[oi] = o;
    split_val(o, gA_hi[oi], gA_lo[oi]);
}

// ---------------- launch ---------------------------------------------------------
extern "C" void kernel_launch(void* const* d_in, const int* in_sizes, int n_in,
                              void* d_out, int out_size){
    const float* adj    = (const float*)d_in[0];
    const float* x      = (const float*)d_in[1];
    const float* W0     = (const float*)d_in[2];
    const float* a_src0 = (const float*)d_in[3];
    const float* a_dst0 = (const float*)d_in[4];
    const float* W1     = (const float*)d_in[5];
    const float* a_src1 = (const float*)d_in[6];
    const float* a_dst1 = (const float*)d_in[7];
    const float* W2     = (const float*)d_in[8];
    const float* a_src2 = (const float*)d_in[9];
    const float* a_dst2 = (const float*)d_in[10];
    const float* ln_g   = (const float*)d_in[11];
    const float* ln_b   = (const float*)d_in[12];
    const float* ff_w1  = (const float*)d_in[13];
    const float* ff_b1  = (const float*)d_in[14];
    const float* ff_w2  = (const float*)d_in[15];
    const float* ff_b2  = (const float*)d_in[16];
    float* out = (float*)d_out;

    float *p_hp, *p_h, *p_ln, *p_part;
    __nv_bfloat16 *pAh, *pAl, *pFh, *pFl;
    __nv_bfloat16 *pw0h,*pw0l,*pw1h,*pw1l,*pw2h,*pw2l,*pf1h,*pf1l,*pf2h,*pf2l;
    cudaGetSymbolAddress((void**)&p_hp,  g_hp);
    cudaGetSymbolAddress((void**)&p_h,   g_h);
    cudaGetSymbolAddress((void**)&p_ln,  g_ln);
    cudaGetSymbolAddress((void**)&p_part, g_part);
    cudaGetSymbolAddress((void**)&pAh, gA_hi);  cudaGetSymbolAddress((void**)&pAl, gA_lo);
    cudaGetSymbolAddress((void**)&pFh, gF_hi);  cudaGetSymbolAddress((void**)&pFl, gF_lo);
    cudaGetSymbolAddress((void**)&pw0h, w0_hi); cudaGetSymbolAddress((void**)&pw0l, w0_lo);
    cudaGetSymbolAddress((void**)&pw1h, w1_hi); cudaGetSymbolAddress((void**)&pw1l, w1_lo);
    cudaGetSymbolAddress((void**)&pw2h, w2_hi); cudaGetSymbolAddress((void**)&pw2l, w2_lo);
    cudaGetSymbolAddress((void**)&pf1h, f1_hi); cudaGetSymbolAddress((void**)&pf1l, f1_lo);
    cudaGetSymbolAddress((void**)&pf2h, f2_hi); cudaGetSymbolAddress((void**)&pf2l, f2_lo);

    const int SM64  = 3*(2*128*40*2 + 2*64*40*2);    // 92160
    cudaFuncSetAttribute(gemm_mma<4,64>, cudaFuncAttributeMaxDynamicSharedMemorySize, SM64);
    cudaFuncSetAttribute(gemm_mma<0,64>, cudaFuncAttributeMaxDynamicSharedMemorySize, SM64);
    cudaFuncSetAttribute(gemm_mma<2,64>, cudaFuncAttributeMaxDynamicSharedMemorySize, SM64);
    cudaFuncSetAttribute(gemm_mma<1,64>, cudaFuncAttributeMaxDynamicSharedMemorySize, SM64);

    dim3 blk(256);
    prep<<<2688, blk>>>(W0, W1, W2, ff_w1, ff_w2, x, a_src2, a_dst2, adj);

    // ---- GAT layer 0 (GEMM + fused scores) ----
    gemm_mma<4,64><<<dim3(4,32), blk, SM64>>>(pAh, pAl, pw0h, pw0l, nullptr, nullptr,
                                              a_src0, a_dst0, p_hp, nullptr, nullptr, ROWS, DIM, DIM, DIM);
    attn01<false><<<ROWS, blk>>>(x, p_h);

    // ---- GAT layer 1 (GEMM + fused scores; attn also emits layer-2 scores) ----
    gemm_mma<4,64><<<dim3(4,32), blk, SM64>>>(pAh, pAl, pw1h, pw1l, nullptr, nullptr,
                                              a_src1, a_dst1, p_hp, nullptr, nullptr, ROWS, DIM, DIM, DIM);
    attn01<true><<<ROWS, blk>>>(p_h, p_h);

    // ---- GAT layer 2: aggregate, then split-K x4 GEMM ----
    attn2b<<<ROWS, blk>>>();
    gemm_mma<0,64><<<dim3(4,32,4), blk, SM64>>>(pAh, pAl, pw2h, pw2l, nullptr, nullptr,
                                                nullptr, nullptr, p_part, nullptr, nullptr,
                                                ROWS, DIM, HD2, 512);

    // ---- LayerNorm (fused partial-reduce + residual) ----
    layernorm4<<<ROWS, blk>>>(p_h, ln_g, ln_b, p_ln);

    // ---- FFN ----
    gemm_mma<1,64><<<dim3(8,32), blk, SM64>>>(pAh, pAl, pf1h, pf1l, ff_b1, nullptr,
                                              nullptr, nullptr, nullptr, pFh, pFl, ROWS, FFH, DIM, DIM);
    gemm_mma<2,64><<<dim3(4,32), blk, SM64>>>(pFh, pFl, pf2h, pf2l, ff_b2, p_ln,
                                              nullptr, nullptr, out, nullptr, nullptr, ROWS, DIM, FFH, FFH);
}

// round 14
// speedup vs baseline: 1.5191x; 1.5191x over previous
#include <cuda_runtime.h>
#include <cuda_bf16.h>
#include <math.h>
#include <stdint.h>

#define BATCH 4
#define SEQ 1024
#define DIM 256
#define NH 8
#define DH 32
#define ROWS (BATCH*SEQ)      // 4096
#define MAXN 256
#define FFH 512
#define HD2 (NH*DIM)          // 2048

// ---------------- scratch ---------------------------------------------------------
__device__ float g_hp [ROWS*DIM];
__device__ float g_h  [ROWS*DIM];
__device__ float g_ln [ROWS*DIM];
__device__ float g_part[4*ROWS*DIM];        // split-K partials (16 MB)
__device__ __nv_bfloat16 gA_hi[ROWS*HD2];
__device__ __nv_bfloat16 gA_lo[ROWS*HD2];
__device__ __nv_bfloat16 gF_hi[ROWS*FFH];
__device__ __nv_bfloat16 gF_lo[ROWS*FFH];
__device__ __nv_bfloat16 w0_hi[DIM*DIM],  w0_lo[DIM*DIM];
__device__ __nv_bfloat16 w1_hi[DIM*DIM],  w1_lo[DIM*DIM];
__device__ __nv_bfloat16 w2_hi[DIM*HD2],  w2_lo[DIM*HD2];
__device__ __nv_bfloat16 f1_hi[FFH*DIM],  f1_lo[FFH*DIM];
__device__ __nv_bfloat16 f2_hi[DIM*FFH],  f2_lo[DIM*FFH];
__device__ float g_va_src[NH*DIM];
__device__ float g_va_dst[NH*DIM];
__device__ float g_src [ROWS*NH];
__device__ float g_dst [ROWS*NH];
__device__ float g_src2[ROWS*NH];
__device__ float g_dst2[ROWS*NH];
__device__ int   g_nbr[ROWS*MAXN];
__device__ int   g_cnt[ROWS];

// ---------------- helpers ---------------------------------------------------------
__device__ __forceinline__ uint32_t smem_u32(const void* p){
    uint32_t a;
    asm("{ .reg .u64 t; cvta.to.shared.u64 t, %1; cvt.u32.u64 %0, t; }" : "=r"(a) : "l"(p));
    return a;
}
__device__ __forceinline__ void split_val(float v, __nv_bfloat16& hi, __nv_bfloat16& lo){
    hi = __float2bfloat16(v);
    lo = __float2bfloat16(v - __bfloat162float(hi));
}
#define CPA16(dst, src) \
    asm volatile("cp.async.cg.shared.global [%0], [%1], 16;" :: "r"(dst), "l"(src) : "memory")
#define LDSM4(r0,r1,r2,r3,addr) \
    asm volatile("ldmatrix.sync.aligned.m8n8.x4.shared.b16 {%0,%1,%2,%3}, [%4];" \
        : "=r"(r0),"=r"(r1),"=r"(r2),"=r"(r3) : "r"(addr))

__device__ __forceinline__ void mma_bf16(float* c, const uint32_t* a, uint32_t b0, uint32_t b1){
    asm volatile("mma.sync.aligned.m16n8k16.row.col.f32.bf16.bf16.f32 "
        "{%0,%1,%2,%3}, {%4,%5,%6,%7}, {%8,%9}, {%0,%1,%2,%3};"
        : "+f"(c[0]),"+f"(c[1]),"+f"(c[2]),"+f"(c[3])
        : "r"(a[0]),"r"(a[1]),"r"(a[2]),"r"(a[3]), "r"(b0),"r"(b1));
}

// ---------------- HMMA split-bf16 GEMM, TM=128, 3-stage pipeline ------------------
// EPI: 0 plain (z-offset partial); 1 +bias GELU -> bf16 split; 2 +bias+res; 4 plain + fused scores
template<int EPI, int TN>
__global__ __launch_bounds__(256)
void gemm_mma(const __nv_bfloat16* __restrict__ Ah, const __nv_bfloat16* __restrict__ Al,
              const __nv_bfloat16* __restrict__ Bh, const __nv_bfloat16* __restrict__ Bl,
              const float* __restrict__ bias, const float* __restrict__ res,
              const float* __restrict__ asv, const float* __restrict__ adv,
              float* __restrict__ C, __nv_bfloat16* __restrict__ Chi, __nv_bfloat16* __restrict__ Clo,
              int M, int N, int K, int Kloop){
    constexpr int LD   = 40;
    constexpr int A_SZ = 128*LD*2;
    constexpr int B_SZ = TN*LD*2;
    constexpr int BUF  = 2*A_SZ + 2*B_SZ;
    constexpr int NB   = TN/16;
    constexpr int NP   = TN/32;
    extern __shared__ char sm[];
    uint32_t sb = smem_u32(sm);
    int tid = threadIdx.x, lane = tid & 31, wid = tid >> 5;
    int bm = blockIdx.y*128, bn = blockIdx.x*TN;
    int wm = (wid & 3)*32, wn = (wid >> 2)*(TN/2);
    int koff = blockIdx.z * Kloop;
    float acc[2][NB][4] = {};
    int nch = Kloop >> 5;

    auto load_chunk = [&](int c){
        uint32_t s0 = sb + (c % 3)*BUF;
        int k0 = koff + c*32;
        #pragma unroll
        for (int i = 0; i < 2; i++){
            int u = tid + i*256;
            int row = u >> 2, c8 = u & 3;
            uint32_t so = (uint32_t)(row*LD + c8*8)*2;
            size_t go = (size_t)(bm + row)*K + k0 + c8*8;
            CPA16(s0 + so,        Ah + go);
            CPA16(s0 + A_SZ + so, Al + go);
        }
        for (int u = tid; u < TN*4; u += 256){
            int row = u >> 2, c8 = u & 3;
            uint32_t so = (uint32_t)(row*LD + c8*8)*2;
            size_t go = (size_t)(bn + row)*K + k0 + c8*8;
            CPA16(s0 + 2*A_SZ + so,        Bh + go);
            CPA16(s0 + 2*A_SZ + B_SZ + so, Bl + go);
        }
        asm volatile("cp.async.commit_group;" ::: "memory");
    };

    load_chunk(0);
    load_chunk(1);
    for (int c = 0; c < nch; c++){
        if (c + 2 < nch){
            load_chunk(c + 2);
            asm volatile("cp.async.wait_group 2;" ::: "memory");
        } else if (c + 1 < nch){
            asm volatile("cp.async.wait_group 1;" ::: "memory");
        } else {
            asm volatile("cp.async.wait_group 0;" ::: "memory");
        }
        __syncthreads();
        uint32_t sA = sb + (c % 3)*BUF;
        uint32_t sB = sA + 2*A_SZ;
        #pragma unroll
        for (int kk = 0; kk < 32; kk += 16){
            uint32_t ah[2][4], al[2][4];
            #pragma unroll
            for (int mb = 0; mb < 2; mb++){
                uint32_t ad = sA + (uint32_t)(((wm + mb*16 + (lane & 15))*LD + kk + (lane >> 4)*8)*2);
                LDSM4(ah[mb][0],ah[mb][1],ah[mb][2],ah[mb][3], ad);
                LDSM4(al[mb][0],al[mb][1],al[mb][2],al[mb][3], ad + A_SZ);
            }
            #pragma unroll
            for (int p = 0; p < NP; p++){
                uint32_t bd = sB + (uint32_t)(((wn + p*16 + ((lane >> 4) << 3) + (lane & 7))*LD
                                              + kk + ((lane >> 3) & 1)*8)*2);
                uint32_t bh[4], bl[4];
                LDSM4(bh[0],bh[1],bh[2],bh[3], bd);
                LDSM4(bl[0],bl[1],bl[2],bl[3], bd + B_SZ);
                #pragma unroll
                for (int j = 0; j < 2; j++){
                    #pragma unroll
                    for (int mb = 0; mb < 2; mb++){
                        float* a_ = acc[mb][p*2 + j];
                        mma_bf16(a_, ah[mb], bh[2*j], bh[2*j+1]);
                        mma_bf16(a_, ah[mb], bl[2*j], bl[2*j+1]);
                        mma_bf16(a_, al[mb], bh[2*j], bh[2*j+1]);
                    }
                }
            }
        }
        __syncthreads();
    }

    int g = lane >> 2, tg = lane & 3;
    float ca[8], cd[8];
    float sacc[2][2] = {}, dacc[2][2] = {};
    int hidx = 0;
    if (EPI == 4){
        hidx = (bn + wn) >> 5;
        #pragma unroll
        for (int nb = 0; nb < 4; nb++)
            #pragma unroll
            for (int e = 0; e < 2; e++){
                int chi = nb*8 + tg*2 + e;
                ca[nb*2+e] = asv[hidx*DH + chi];
                cd[nb*2+e] = adv[hidx*DH + chi];
            }
    }
    size_t zoff = (EPI == 0) ? (size_t)blockIdx.z * M * N : 0;
    #pragma unroll
    for (int mb = 0; mb < 2; mb++){
        #pragma unroll
        for (int nb = 0; nb < NB; nb++){
            float* a_ = acc[mb][nb];
            int col = bn + wn + nb*8 + tg*2;
            #pragma unroll
            for (int half = 0; half < 2; half++){
                int r = bm + wm + mb*16 + g + half*8;
                size_t ci = (size_t)r*N + col;
                float v0 = a_[half*2], v1 = a_[half*2+1];
                if (EPI == 0){
                    *(float2*)&C[zoff + ci] = make_float2(v0, v1);
                } else if (EPI == 4){
                    *(float2*)&C[ci] = make_float2(v0, v1);
                    sacc[mb][half] = fmaf(v0, ca[nb*2], fmaf(v1, ca[nb*2+1], sacc[mb][half]));
                    dacc[mb][half] = fmaf(v0, cd[nb*2], fmaf(v1, cd[nb*2+1], dacc[mb][half]));
                } else if (EPI == 1){
                    v0 += bias[col]; v1 += bias[col+1];
                    float t0 = 0.7978845608028654f*(v0 + 0.044715f*v0*v0*v0);
                    v0 = 0.5f*v0*(1.f + tanhf(t0));
                    float t1 = 0.7978845608028654f*(v1 + 0.044715f*v1*v1*v1);
                    v1 = 0.5f*v1*(1.f + tanhf(t1));
                    __nv_bfloat16 h0,l0,h1,l1;
                    split_val(v0,h0,l0); split_val(v1,h1,l1);
                    __nv_bfloat162 hp2; hp2.x=h0; hp2.y=h1;
                    __nv_bfloat162 lp2; lp2.x=l0; lp2.y=l1;
                    *(__nv_bfloat162*)&Chi[ci] = hp2;
                    *(__nv_bfloat162*)&Clo[ci] = lp2;
                } else if (EPI == 2){
                    float2 rr = *(const float2*)&res[ci];
                    *(float2*)&C[ci] = make_float2(v0 + bias[col] + rr.x, v1 + bias[col+1] + rr.y);
                }
            }
        }
    }
    if (EPI == 4){
        #pragma unroll
        for (int mb = 0; mb < 2; mb++)
            #pragma unroll
            for (int half = 0; half < 2; half++){
                float s = sacc[mb][half], d = dacc[mb][half];
                s += __shfl_xor_sync(0xffffffffu, s, 1);
                s += __shfl_xor_sync(0xffffffffu, s, 2);
                d += __shfl_xor_sync(0xffffffffu, d, 1);
                d += __shfl_xor_sync(0xffffffffu, d, 2);
                if (tg == 0){
                    int r = bm + wm + mb*16 + g + half*8;
                    g_src[r*NH + hidx] = s;
                    g_dst[r*NH + hidx] = d;
                }
            }
    }
}

// ---------------- merged prep ----------------------------------------------------
__device__ __forceinline__ void trans_tile(const float* __restrict__ inp, int ldi,
                                           __nv_bfloat16* __restrict__ oh, __nv_bfloat16* __restrict__ ol,
                                           int ldo, int kt, int nt, float scale){
    __shared__ float tile[32][33];
    int tx = threadIdx.x & 31, ty0 = threadIdx.x >> 5;
    #pragma unroll
    for (int i = 0; i < 4; i++){
        int ty = ty0 + i*8;
        tile[ty][tx] = inp[(size_t)(kt*32 + ty)*ldi + nt*32 + tx];
    }
    __syncthreads();
    #pragma unroll
    for (int i = 0; i < 4; i++){
        int ty = ty0 + i*8;
        float v = scale * tile[tx][ty];
        size_t oi = (size_t)(nt*32 + ty)*ldo + kt*32 + tx;
        __nv_bfloat16 hi, lo; split_val(v, hi, lo);
        oh[oi] = hi; ol[oi] = lo;
    }
}

__global__ __launch_bounds__(256)
void prep(const float* __restrict__ W0, const float* __restrict__ W1, const float* __restrict__ W2,
          const float* __restrict__ F1, const float* __restrict__ F2,
          const float* __restrict__ x,
          const float* __restrict__ as2, const float* __restrict__ ad2,
          const float* __restrict__ adj){
    int b = blockIdx.x, tid = threadIdx.x;
    if (b < 64){
        trans_tile(W0, DIM, w0_hi, w0_lo, DIM, b >> 3, b & 7, 1.f);
    } else if (b < 128){
        int t = b - 64;
        trans_tile(W1, DIM, w1_hi, w1_lo, DIM, t >> 3, t & 7, 1.f);
    } else if (b < 640){
        int rel = b - 128, h = rel >> 6, t = rel & 63;
        trans_tile(W2 + h*DIM, HD2, w2_hi + h*DIM, w2_lo + h*DIM, HD2, t >> 3, t & 7, 0.125f);
    } else if (b < 768){
        int rel = b - 640;
        trans_tile(F1, FFH, f1_hi, f1_lo, DIM, rel >> 4, rel & 15, 1.f);
    } else if (b < 896){
        int rel = b - 768;
        trans_tile(F2, DIM, f2_hi, f2_lo, FFH, rel >> 3, rel & 7, 1.f);
    } else if (b < 1920){
        int idx4 = (b - 896)*256 + tid;
        float4 v = *(const float4*)&x[idx4*4];
        __nv_bfloat16 h0,l0,h1,l1,h2,l2,h3,l3;
        split_val(v.x,h0,l0); split_val(v.y,h1,l1);
        split_val(v.z,h2,l2); split_val(v.w,h3,l3);
        __nv_bfloat162 ha; ha.x=h0; ha.y=h1;
        __nv_bfloat162 hb; hb.x=h2; hb.y=h3;
        __nv_bfloat162 la; la.x=l0; la.y=l1;
        __nv_bfloat162 lb; lb.x=l2; lb.y=l3;
        *(__nv_bfloat162*)&gA_hi[idx4*4]   = ha;
        *(__nv_bfloat162*)&gA_hi[idx4*4+2] = hb;
        *(__nv_bfloat162*)&gA_lo[idx4*4]   = la;
        *(__nv_bfloat162*)&gA_lo[idx4*4+2] = lb;
    } else if (b < 2176){
        int rel = b - 1920;
        int gw = rel*8 + (tid >> 5);
        int lane = tid & 31;
        int h = gw >> 8, c = gw & 255;
        float s = 0.f, t = 0.f;
        #pragma unroll
        for (int d = lane; d < DIM; d += 32){
            float wv = W2[(size_t)c*HD2 + h*DIM + d];
            s += wv * as2[h*DIM + d];
            t += wv * ad2[h*DIM + d];
        }
        #pragma unroll
        for (int o = 16; o > 0; o >>= 1){
            s += __shfl_down_sync(0xffffffffu, s, o);
            t += __shfl_down_sync(0xffffffffu, t, o);
        }
        if (lane == 0){ g_va_src[h*DIM + c] = s; g_va_dst[h*DIM + c] = t; }
    } else {
        // adj scan: warp per row, float4 loads (deterministic interleaved order)
        int row = (b - 2176)*8 + (tid >> 5);
        int lane = tid & 31;
        const float* arow = adj + (size_t)row * SEQ;
        int cnt = 0;
        for (int base = 0; base < SEQ; base += 128){
            float4 v = *(const float4*)&arow[base + lane*4];
            float vv[4] = {v.x, v.y, v.z, v.w};
            #pragma unroll
            for (int i = 0; i < 4; i++){
                bool p = vv[i] > 0.f;
                unsigned m = __ballot_sync(0xffffffffu, p);
                if (p){
                    int pos = cnt + __popc(m & ((1u << lane) - 1u));
                    if (pos < MAXN) g_nbr[row*MAXN + pos] = base + lane*4 + i;
                }
                cnt += __popc(m);
            }
        }
        if (lane == 0) g_cnt[row] = cnt < MAXN ? cnt : MAXN;
    }
}

// ---------------- softmax weights -------------------------------------------------
__device__ __forceinline__ void compute_weights(int row, int b, int cnt,
                                                const int* nbr, float* w, float* srcI,
                                                const float* __restrict__ srcA,
                                                const float* __restrict__ dstA){
    int tid = threadIdx.x;
    if (tid < NH) srcI[tid] = srcA[row*NH + tid];
    __syncthreads();
    for (int idx = tid; idx < cnt*NH; idx += 256){
        int n = idx >> 3, h = idx & 7;
        float e = srcI[h] + dstA[(size_t)(b*SEQ + nbr[n])*NH + h];
        w[n*NH + h] = e > 0.f ? e : 0.2f*e;
    }
    __syncthreads();
    int h = tid >> 5, lane = tid & 31;
    float m = -1e30f;
    for (int n = lane; n < cnt; n += 32) m = fmaxf(m, w[n*NH + h]);
    #pragma unroll
    for (int o = 16; o > 0; o >>= 1) m = fmaxf(m, __shfl_xor_sync(0xffffffffu, m, o));
    float ssum = 0.f;
    for (int n = lane; n < cnt; n += 32){
        float e = expf(w[n*NH + h] - m);
        w[n*NH + h] = e;
        ssum += e;
    }
    #pragma unroll
    for (int o = 16; o > 0; o >>= 1) ssum += __shfl_xor_sync(0xffffffffu, ssum, o);
    float inv = 1.f / ssum;
    for (int n = lane; n < cnt; n += 32) w[n*NH + h] *= inv;
    __syncthreads();
}

// aggregate (float4, 4-group) + residual + ELU (+optionally fused layer-2 scores)
template<bool S2>
__global__ __launch_bounds__(256)
void attn01(const float* __restrict__ resid, float* __restrict__ out){
    int row = blockIdx.x;
    int b = row / SEQ;
    int tid = threadIdx.x;
    int cnt = g_cnt[row];
    __shared__ int   nbr[MAXN];
    __shared__ float w[MAXN*NH];
    __shared__ float srcI[NH];
    __shared__ float sred[4][DIM];
    __shared__ float val[DIM];
    for (int n = tid; n < cnt; n += 256) nbr[n] = g_nbr[row*MAXN + n];
    __syncthreads();
    compute_weights(row, b, cnt, nbr, w, srcI, g_src, g_dst);

    int g4 = tid >> 6, c4 = tid & 63;
    int ch0 = c4*4;
    int hh = c4 >> 3;
    float a0 = 0.f, a1 = 0.f, a2 = 0.f, a3 = 0.f;
    float b0_ = 0.f, b1_ = 0.f, b2_ = 0.f, b3_ = 0.f;
    int n = g4;
    for (; n + 4 < cnt; n += 8){
        int j0 = nbr[n], j1 = nbr[n+4];
        float4 v0 = *(const float4*)&g_hp[((size_t)(b*SEQ + j0))*DIM + ch0];
        float4 v1 = *(const float4*)&g_hp[((size_t)(b*SEQ + j1))*DIM + ch0];
        float wt0 = w[n*NH + hh];
        float wt1 = w[(n+4)*NH + hh];
        a0 = fmaf(wt0, v0.x, a0); a1 = fmaf(wt0, v0.y, a1);
        a2 = fmaf(wt0, v0.z, a2); a3 = fmaf(wt0, v0.w, a3);
        b0_ = fmaf(wt1, v1.x, b0_); b1_ = fmaf(wt1, v1.y, b1_);
        b2_ = fmaf(wt1, v1.z, b2_); b3_ = fmaf(wt1, v1.w, b3_);
    }
    if (n < cnt){
        int j0 = nbr[n];
        float4 v0 = *(const float4*)&g_hp[((size_t)(b*SEQ + j0))*DIM + ch0];
        float wt0 = w[n*NH + hh];
        a0 = fmaf(wt0, v0.x, a0); a1 = fmaf(wt0, v0.y, a1);
        a2 = fmaf(wt0, v0.z, a2); a3 = fmaf(wt0, v0.w, a3);
    }
    a0 += b0_; a1 += b1_; a2 += b2_; a3 += b3_;
    *(float4*)&sred[g4][ch0] = make_float4(a0, a1, a2, a3);
    __syncthreads();

    int ch = tid;
    float acc = sred[0][ch] + sred[1][ch] + sred[2][ch] + sred[3][ch];
    size_t oi = (size_t)row*DIM + ch;
    float v = acc + resid[oi];
    v = v > 0.f ? v : expm1f(v);
    out[oi] = v;
    if (!S2){
        split_val(v, gA_hi[oi], gA_lo[oi]);
    } else {
        val[ch] = v;
        __syncthreads();
        int h = tid >> 5, lane = tid & 31;
        float s = 0.f, t = 0.f;
        #pragma unroll
        for (int d = lane; d < DIM; d += 32){
            float vd = val[d];
            s = fmaf(vd, g_va_src[h*DIM + d], s);
            t = fmaf(vd, g_va_dst[h*DIM + d], t);
        }
        #pragma unroll
        for (int o = 16; o > 0; o >>= 1){
            s += __shfl_down_sync(0xffffffffu, s, o);
            t += __shfl_down_sync(0xffffffffu, t, o);
        }
        if (lane == 0){ g_src2[row*NH + h] = s; g_dst2[row*NH + h] = t; }
    }
}

// layer 2: aggregate h per head (R12-proven: vectorized weight loads, scalar acc)
__global__ __launch_bounds__(256)
void attn2b(){
    int row = blockIdx.x;
    int b = row / SEQ;
    int tid = threadIdx.x;
    int cnt = g_cnt[row];
    __shared__ int   nbr[MAXN];
    __shared__ float w[MAXN*NH];
    __shared__ float srcI[NH];
    for (int n = tid; n < cnt; n += 256) nbr[n] = g_nbr[row*MAXN + n];
    __syncthreads();
    compute_weights(row, b, cnt, nbr, w, srcI, g_src2, g_dst2);
    int c = tid;
    float acc[NH] = {};
    int n = 0;
    for (; n + 2 <= cnt; n += 2){
        int j0 = nbr[n], j1 = nbr[n+1];
        float v0 = g_h[(size_t)(b*SEQ + j0)*DIM + c];
        float v1 = g_h[(size_t)(b*SEQ + j1)*DIM + c];
        float4 wa0 = *(const float4*)&w[n*NH];
        float4 wb0 = *(const float4*)&w[n*NH + 4];
        float4 wa1 = *(const float4*)&w[(n+1)*NH];
        float4 wb1 = *(const float4*)&w[(n+1)*NH + 4];
        acc[0] = fmaf(wa0.x, v0, acc[0]); acc[1] = fmaf(wa0.y, v0, acc[1]);
        acc[2] = fmaf(wa0.z, v0, acc[2]); acc[3] = fmaf(wa0.w, v0, acc[3]);
        acc[4] = fmaf(wb0.x, v0, acc[4]); acc[5] = fmaf(wb0.y, v0, acc[5]);
        acc[6] = fmaf(wb0.z, v0, acc[6]); acc[7] = fmaf(wb0.w, v0, acc[7]);
        acc[0] = fmaf(wa1.x, v1, acc[0]); acc[1] = fmaf(wa1.y, v1, acc[1]);
        acc[2] = fmaf(wa1.z, v1, acc[2]); acc[3] = fmaf(wa1.w, v1, acc[3]);
        acc[4] = fmaf(wb1.x, v1, acc[4]); acc[5] = fmaf(wb1.y, v1, acc[5]);
        acc[6] = fmaf(wb1.z, v1, acc[6]); acc[7] = fmaf(wb1.w, v1, acc[7]);
    }
    for (; n < cnt; n++){
        float v = g_h[(size_t)(b*SEQ + nbr[n])*DIM + c];
        float4 wa = *(const float4*)&w[n*NH];
        float4 wb = *(const float4*)&w[n*NH + 4];
        acc[0] = fmaf(wa.x, v, acc[0]); acc[1] = fmaf(wa.y, v, acc[1]);
        acc[2] = fmaf(wa.z, v, acc[2]); acc[3] = fmaf(wa.w, v, acc[3]);
        acc[4] = fmaf(wb.x, v, acc[4]); acc[5] = fmaf(wb.y, v, acc[5]);
        acc[6] = fmaf(wb.z, v, acc[6]); acc[7] = fmaf(wb.w, v, acc[7]);
    }
    #pragma unroll
    for (int h = 0; h < NH; h++){
        size_t oi = (size_t)row*HD2 + h*DIM + c;
        split_val(acc[h], gA_hi[oi], gA_lo[oi]);
    }
}

// ---------------- LayerNorm over sum of 4 split-K partials + residual -------------
__global__ void layernorm4(const float* __restrict__ res,
                           const float* __restrict__ ln_g, const float* __restrict__ ln_b,
                           float* __restrict__ out){
    int row = blockIdx.x, tid = threadIdx.x;
    size_t oi = (size_t)row*DIM + tid;
    float v = g_part[oi] + g_part[oi + (size_t)ROWS*DIM]
            + g_part[oi + 2*(size_t)ROWS*DIM] + g_part[oi + 3*(size_t)ROWS*DIM]
            + res[oi];
    __shared__ float red[8];
    __shared__ float mu, rstd;
    float s = v;
    #pragma unroll
    for (int o = 16; o > 0; o >>= 1) s += __shfl_xor_sync(0xffffffffu, s, o);
    if ((tid & 31) == 0) red[tid >> 5] = s;
    __syncthreads();
    if (tid == 0){ float t = 0.f; for (int i = 0; i < 8; i++) t += red[i]; mu = t / 256.f; }
    __syncthreads();
    float d = v - mu;
    s = d*d;
    #pragma unroll
    for (int o = 16; o > 0; o >>= 1) s += __shfl_xor_sync(0xffffffffu, s, o);
    if ((tid & 31) == 0) red[tid >> 5] = s;
    __syncthreads();
    if (tid == 0){ float t = 0.f; for (int i = 0; i < 8; i++) t += red[i]; rstd = rsqrtf(t/256.f + 1e-5f); }
    __syncthreads();
    float o = d*rstd*ln_g[tid] + ln_b[tid];
    out[oi] = o;
    split_val(o, gA_hi[oi], gA_lo[oi]);
}

// ---------------- launch ---------------------------------------------------------
extern "C" void kernel_launch(void* const* d_in, const int* in_sizes, int n_in,
                              void* d_out, int out_size){
    const float* adj    = (const float*)d_in[0];
    const float* x      = (const float*)d_in[1];
    const float* W0     = (const float*)d_in[2];
    const float* a_src0 = (const float*)d_in[3];
    const float* a_dst0 = (const float*)d_in[4];
    const float* W1     = (const float*)d_in[5];
    const float* a_src1 = (const float*)d_in[6];
    const float* a_dst1 = (const float*)d_in[7];
    const float* W2     = (const float*)d_in[8];
    const float* a_src2 = (const float*)d_in[9];
    const float* a_dst2 = (const float*)d_in[10];
    const float* ln_g   = (const float*)d_in[11];
    const float* ln_b   = (const float*)d_in[12];
    const float* ff_w1  = (const float*)d_in[13];
    const float* ff_b1  = (const float*)d_in[14];
    const float* ff_w2  = (const float*)d_in[15];
    const float* ff_b2  = (const float*)d_in[16];
    float* out = (float*)d_out;

    float *p_hp, *p_h, *p_ln, *p_part;
    __nv_bfloat16 *pAh, *pAl, *pFh, *pFl;
    __nv_bfloat16 *pw0h,*pw0l,*pw1h,*pw1l,*pw2h,*pw2l,*pf1h,*pf1l,*pf2h,*pf2l;
    cudaGetSymbolAddress((void**)&p_hp,  g_hp);
    cudaGetSymbolAddress((void**)&p_h,   g_h);
    cudaGetSymbolAddress((void**)&p_ln,  g_ln);
    cudaGetSymbolAddress((void**)&p_part, g_part);
    cudaGetSymbolAddress((void**)&pAh, gA_hi);  cudaGetSymbolAddress((void**)&pAl, gA_lo);
    cudaGetSymbolAddress((void**)&pFh, gF_hi);  cudaGetSymbolAddress((void**)&pFl, gF_lo);
    cudaGetSymbolAddress((void**)&pw0h, w0_hi); cudaGetSymbolAddress((void**)&pw0l, w0_lo);
    cudaGetSymbolAddress((void**)&pw1h, w1_hi); cudaGetSymbolAddress((void**)&pw1l, w1_lo);
    cudaGetSymbolAddress((void**)&pw2h, w2_hi); cudaGetSymbolAddress((void**)&pw2l, w2_lo);
    cudaGetSymbolAddress((void**)&pf1h, f1_hi); cudaGetSymbolAddress((void**)&pf1l, f1_lo);
    cudaGetSymbolAddress((void**)&pf2h, f2_hi); cudaGetSymbolAddress((void**)&pf2l, f2_lo);

    const int SM64  = 3*(2*128*40*2 + 2*64*40*2);    // 92160
    cudaFuncSetAttribute(gemm_mma<4,64>, cudaFuncAttributeMaxDynamicSharedMemorySize, SM64);
    cudaFuncSetAttribute(gemm_mma<0,64>, cudaFuncAttributeMaxDynamicSharedMemorySize, SM64);
    cudaFuncSetAttribute(gemm_mma<2,64>, cudaFuncAttributeMaxDynamicSharedMemorySize, SM64);
    cudaFuncSetAttribute(gemm_mma<1,64>, cudaFuncAttributeMaxDynamicSharedMemorySize, SM64);

    dim3 blk(256);
    prep<<<2688, blk>>>(W0, W1, W2, ff_w1, ff_w2, x, a_src2, a_dst2, adj);

    // ---- GAT layer 0 (GEMM + fused scores) ----
    gemm_mma<4,64><<<dim3(4,32), blk, SM64>>>(pAh, pAl, pw0h, pw0l, nullptr, nullptr,
                                              a_src0, a_dst0, p_hp, nullptr, nullptr, ROWS, DIM, DIM, DIM);
    attn01<false><<<ROWS, blk>>>(x, p_h);

    // ---- GAT layer 1 (GEMM + fused scores; attn also emits layer-2 scores) ----
    gemm_mma<4,64><<<dim3(4,32), blk, SM64>>>(pAh, pAl, pw1h, pw1l, nullptr, nullptr,
                                              a_src1, a_dst1, p_hp, nullptr, nullptr, ROWS, DIM, DIM, DIM);
    attn01<true><<<ROWS, blk>>>(p_h, p_h);

    // ---- GAT layer 2: aggregate, then split-K x4 GEMM ----
    attn2b<<<ROWS, blk>>>();
    gemm_mma<0,64><<<dim3(4,32,4), blk, SM64>>>(pAh, pAl, pw2h, pw2l, nullptr, nullptr,
                                                nullptr, nullptr, p_part, nullptr, nullptr,
                                                ROWS, DIM, HD2, 512);

    // ---- LayerNorm (fused partial-reduce + residual) ----
    layernorm4<<<ROWS, blk>>>(p_h, ln_g, ln_b, p_ln);

    // ---- FFN ----
    gemm_mma<1,64><<<dim3(8,32), blk, SM64>>>(pAh, pAl, pf1h, pf1l, ff_b1, nullptr,
                                              nullptr, nullptr, nullptr, pFh, pFl, ROWS, FFH, DIM, DIM);
    gemm_mma<2,64><<<dim3(4,32), blk, SM64>>>(pFh, pFl, pf2h, pf2l, ff_b2, p_ln,
                                              nullptr, nullptr, out, nullptr, nullptr, ROWS, DIM, FFH, FFH);
}

// round 15
// speedup vs baseline: 1.5438x; 1.0163x over previous
#include <cuda_runtime.h>
#include <cuda_bf16.h>
#include <math.h>
#include <stdint.h>

#define BATCH 4
#define SEQ 1024
#define DIM 256
#define NH 8
#define DH 32
#define ROWS (BATCH*SEQ)      // 4096
#define MAXN 256
#define FFH 512
#define HD2 (NH*DIM)          // 2048

// ---------------- scratch ---------------------------------------------------------
__device__ float g_hp [ROWS*DIM];
__device__ float g_h  [ROWS*DIM];
__device__ float g_ln [ROWS*DIM];
__device__ float g_part[4*ROWS*DIM];        // split-K partials (16 MB)
__device__ __nv_bfloat16 gA_hi[ROWS*HD2];
__device__ __nv_bfloat16 gA_lo[ROWS*HD2];
__device__ __nv_bfloat16 gF_hi[ROWS*FFH];
__device__ __nv_bfloat16 gF_lo[ROWS*FFH];
__device__ __nv_bfloat16 w0_hi[DIM*DIM],  w0_lo[DIM*DIM];
__device__ __nv_bfloat16 w1_hi[DIM*DIM],  w1_lo[DIM*DIM];
__device__ __nv_bfloat16 w2_hi[DIM*HD2],  w2_lo[DIM*HD2];
__device__ __nv_bfloat16 f1_hi[FFH*DIM],  f1_lo[FFH*DIM];
__device__ __nv_bfloat16 f2_hi[DIM*FFH],  f2_lo[DIM*FFH];
__device__ float g_va_src[NH*DIM];
__device__ float g_va_dst[NH*DIM];
__device__ float g_src [ROWS*NH];
__device__ float g_dst [ROWS*NH];
__device__ float g_src2[ROWS*NH];
__device__ float g_dst2[ROWS*NH];
__device__ int   g_nbr[ROWS*MAXN];
__device__ int   g_cnt[ROWS];

// ---------------- helpers ---------------------------------------------------------
__device__ __forceinline__ uint32_t smem_u32(const void* p){
    uint32_t a;
    asm("{ .reg .u64 t; cvta.to.shared.u64 t, %1; cvt.u32.u64 %0, t; }" : "=r"(a) : "l"(p));
    return a;
}
__device__ __forceinline__ void split_val(float v, __nv_bfloat16& hi, __nv_bfloat16& lo){
    hi = __float2bfloat16(v);
    lo = __float2bfloat16(v - __bfloat162float(hi));
}
#define CPA16(dst, src) \
    asm volatile("cp.async.cg.shared.global [%0], [%1], 16;" :: "r"(dst), "l"(src) : "memory")
#define LDSM4(r0,r1,r2,r3,addr) \
    asm volatile("ldmatrix.sync.aligned.m8n8.x4.shared.b16 {%0,%1,%2,%3}, [%4];" \
        : "=r"(r0),"=r"(r1),"=r"(r2),"=r"(r3) : "r"(addr))

__device__ __forceinline__ void mma_bf16(float* c, const uint32_t* a, uint32_t b0, uint32_t b1){
    asm volatile("mma.sync.aligned.m16n8k16.row.col.f32.bf16.bf16.f32 "
        "{%0,%1,%2,%3}, {%4,%5,%6,%7}, {%8,%9}, {%0,%1,%2,%3};"
        : "+f"(c[0]),"+f"(c[1]),"+f"(c[2]),"+f"(c[3])
        : "r"(a[0]),"r"(a[1]),"r"(a[2]),"r"(a[3]), "r"(b0),"r"(b1));
}

// ---------------- HMMA split-bf16 GEMM, TM=128, 3-stage pipeline ------------------
// EPI: 0 plain (z-offset partial); 1 +bias GELU -> bf16 split; 2 +bias+res; 4 plain + fused scores
template<int EPI, int TN>
__global__ __launch_bounds__(256)
void gemm_mma(const __nv_bfloat16* __restrict__ Ah, const __nv_bfloat16* __restrict__ Al,
              const __nv_bfloat16* __restrict__ Bh, const __nv_bfloat16* __restrict__ Bl,
              const float* __restrict__ bias, const float* __restrict__ res,
              const float* __restrict__ asv, const float* __restrict__ adv,
              float* __restrict__ C, __nv_bfloat16* __restrict__ Chi, __nv_bfloat16* __restrict__ Clo,
              int M, int N, int K, int Kloop){
    constexpr int LD   = 40;
    constexpr int A_SZ = 128*LD*2;
    constexpr int B_SZ = TN*LD*2;
    constexpr int BUF  = 2*A_SZ + 2*B_SZ;
    constexpr int NB   = TN/16;
    constexpr int NP   = TN/32;
    extern __shared__ char sm[];
    uint32_t sb = smem_u32(sm);
    int tid = threadIdx.x, lane = tid & 31, wid = tid >> 5;
    int bm = blockIdx.y*128, bn = blockIdx.x*TN;
    int wm = (wid & 3)*32, wn = (wid >> 2)*(TN/2);
    int koff = blockIdx.z * Kloop;
    float acc[2][NB][4] = {};
    int nch = Kloop >> 5;

    auto load_chunk = [&](int c){
        uint32_t s0 = sb + (c % 3)*BUF;
        int k0 = koff + c*32;
        #pragma unroll
        for (int i = 0; i < 2; i++){
            int u = tid + i*256;
            int row = u >> 2, c8 = u & 3;
            uint32_t so = (uint32_t)(row*LD + c8*8)*2;
            size_t go = (size_t)(bm + row)*K + k0 + c8*8;
            CPA16(s0 + so,        Ah + go);
            CPA16(s0 + A_SZ + so, Al + go);
        }
        for (int u = tid; u < TN*4; u += 256){
            int row = u >> 2, c8 = u & 3;
            uint32_t so = (uint32_t)(row*LD + c8*8)*2;
            size_t go = (size_t)(bn + row)*K + k0 + c8*8;
            CPA16(s0 + 2*A_SZ + so,        Bh + go);
            CPA16(s0 + 2*A_SZ + B_SZ + so, Bl + go);
        }
        asm volatile("cp.async.commit_group;" ::: "memory");
    };

    load_chunk(0);
    load_chunk(1);
    for (int c = 0; c < nch; c++){
        if (c + 2 < nch){
            load_chunk(c + 2);
            asm volatile("cp.async.wait_group 2;" ::: "memory");
        } else if (c + 1 < nch){
            asm volatile("cp.async.wait_group 1;" ::: "memory");
        } else {
            asm volatile("cp.async.wait_group 0;" ::: "memory");
        }
        __syncthreads();
        uint32_t sA = sb + (c % 3)*BUF;
        uint32_t sB = sA + 2*A_SZ;
        #pragma unroll
        for (int kk = 0; kk < 32; kk += 16){
            uint32_t ah[2][4], al[2][4];
            #pragma unroll
            for (int mb = 0; mb < 2; mb++){
                uint32_t ad = sA + (uint32_t)(((wm + mb*16 + (lane & 15))*LD + kk + (lane >> 4)*8)*2);
                LDSM4(ah[mb][0],ah[mb][1],ah[mb][2],ah[mb][3], ad);
                LDSM4(al[mb][0],al[mb][1],al[mb][2],al[mb][3], ad + A_SZ);
            }
            #pragma unroll
            for (int p = 0; p < NP; p++){
                uint32_t bd = sB + (uint32_t)(((wn + p*16 + ((lane >> 4) << 3) + (lane & 7))*LD
                                              + kk + ((lane >> 3) & 1)*8)*2);
                uint32_t bh[4], bl[4];
                LDSM4(bh[0],bh[1],bh[2],bh[3], bd);
                LDSM4(bl[0],bl[1],bl[2],bl[3], bd + B_SZ);
                #pragma unroll
                for (int j = 0; j < 2; j++){
                    #pragma unroll
                    for (int mb = 0; mb < 2; mb++){
                        float* a_ = acc[mb][p*2 + j];
                        mma_bf16(a_, ah[mb], bh[2*j], bh[2*j+1]);
                        mma_bf16(a_, ah[mb], bl[2*j], bl[2*j+1]);
                        mma_bf16(a_, al[mb], bh[2*j], bh[2*j+1]);
                    }
                }
            }
        }
        __syncthreads();
    }

    int g = lane >> 2, tg = lane & 3;
    float ca[8], cd[8];
    float sacc[2][2] = {}, dacc[2][2] = {};
    int hidx = 0;
    if (EPI == 4){
        hidx = (bn + wn) >> 5;
        #pragma unroll
        for (int nb = 0; nb < 4; nb++)
            #pragma unroll
            for (int e = 0; e < 2; e++){
                int chi = nb*8 + tg*2 + e;
                ca[nb*2+e] = asv[hidx*DH + chi];
                cd[nb*2+e] = adv[hidx*DH + chi];
            }
    }
    size_t zoff = (EPI == 0) ? (size_t)blockIdx.z * M * N : 0;
    #pragma unroll
    for (int mb = 0; mb < 2; mb++){
        #pragma unroll
        for (int nb = 0; nb < NB; nb++){
            float* a_ = acc[mb][nb];
            int col = bn + wn + nb*8 + tg*2;
            #pragma unroll
            for (int half = 0; half < 2; half++){
                int r = bm + wm + mb*16 + g + half*8;
                size_t ci = (size_t)r*N + col;
                float v0 = a_[half*2], v1 = a_[half*2+1];
                if (EPI == 0){
                    *(float2*)&C[zoff + ci] = make_float2(v0, v1);
                } else if (EPI == 4){
                    *(float2*)&C[ci] = make_float2(v0, v1);
                    sacc[mb][half] = fmaf(v0, ca[nb*2], fmaf(v1, ca[nb*2+1], sacc[mb][half]));
                    dacc[mb][half] = fmaf(v0, cd[nb*2], fmaf(v1, cd[nb*2+1], dacc[mb][half]));
                } else if (EPI == 1){
                    v0 += bias[col]; v1 += bias[col+1];
                    float t0 = 0.7978845608028654f*(v0 + 0.044715f*v0*v0*v0);
                    v0 = 0.5f*v0*(1.f + tanhf(t0));
                    float t1 = 0.7978845608028654f*(v1 + 0.044715f*v1*v1*v1);
                    v1 = 0.5f*v1*(1.f + tanhf(t1));
                    __nv_bfloat16 h0,l0,h1,l1;
                    split_val(v0,h0,l0); split_val(v1,h1,l1);
                    __nv_bfloat162 hp2; hp2.x=h0; hp2.y=h1;
                    __nv_bfloat162 lp2; lp2.x=l0; lp2.y=l1;
                    *(__nv_bfloat162*)&Chi[ci] = hp2;
                    *(__nv_bfloat162*)&Clo[ci] = lp2;
                } else if (EPI == 2){
                    float2 rr = *(const float2*)&res[ci];
                    *(float2*)&C[ci] = make_float2(v0 + bias[col] + rr.x, v1 + bias[col+1] + rr.y);
                }
            }
        }
    }
    if (EPI == 4){
        #pragma unroll
        for (int mb = 0; mb < 2; mb++)
            #pragma unroll
            for (int half = 0; half < 2; half++){
                float s = sacc[mb][half], d = dacc[mb][half];
                s += __shfl_xor_sync(0xffffffffu, s, 1);
                s += __shfl_xor_sync(0xffffffffu, s, 2);
                d += __shfl_xor_sync(0xffffffffu, d, 1);
                d += __shfl_xor_sync(0xffffffffu, d, 2);
                if (tg == 0){
                    int r = bm + wm + mb*16 + g + half*8;
                    g_src[r*NH + hidx] = s;
                    g_dst[r*NH + hidx] = d;
                }
            }
    }
}

// ---------------- merged prep ----------------------------------------------------
__device__ __forceinline__ void trans_tile(const float* __restrict__ inp, int ldi,
                                           __nv_bfloat16* __restrict__ oh, __nv_bfloat16* __restrict__ ol,
                                           int ldo, int kt, int nt, float scale){
    __shared__ float tile[32][33];
    int tx = threadIdx.x & 31, ty0 = threadIdx.x >> 5;
    #pragma unroll
    for (int i = 0; i < 4; i++){
        int ty = ty0 + i*8;
        tile[ty][tx] = inp[(size_t)(kt*32 + ty)*ldi + nt*32 + tx];
    }
    __syncthreads();
    #pragma unroll
    for (int i = 0; i < 4; i++){
        int ty = ty0 + i*8;
        float v = scale * tile[tx][ty];
        size_t oi = (size_t)(nt*32 + ty)*ldo + kt*32 + tx;
        __nv_bfloat16 hi, lo; split_val(v, hi, lo);
        oh[oi] = hi; ol[oi] = lo;
    }
}

__global__ __launch_bounds__(256)
void prep(const float* __restrict__ W0, const float* __restrict__ W1, const float* __restrict__ W2,
          const float* __restrict__ F1, const float* __restrict__ F2,
          const float* __restrict__ x,
          const float* __restrict__ as2, const float* __restrict__ ad2,
          const float* __restrict__ adj){
    int b = blockIdx.x, tid = threadIdx.x;
    if (b < 64){
        trans_tile(W0, DIM, w0_hi, w0_lo, DIM, b >> 3, b & 7, 1.f);
    } else if (b < 128){
        int t = b - 64;
        trans_tile(W1, DIM, w1_hi, w1_lo, DIM, t >> 3, t & 7, 1.f);
    } else if (b < 640){
        int rel = b - 128, h = rel >> 6, t = rel & 63;
        trans_tile(W2 + h*DIM, HD2, w2_hi + h*DIM, w2_lo + h*DIM, HD2, t >> 3, t & 7, 0.125f);
    } else if (b < 768){
        int rel = b - 640;
        trans_tile(F1, FFH, f1_hi, f1_lo, DIM, rel >> 4, rel & 15, 1.f);
    } else if (b < 896){
        int rel = b - 768;
        trans_tile(F2, DIM, f2_hi, f2_lo, FFH, rel >> 3, rel & 7, 1.f);
    } else if (b < 1920){
        int idx4 = (b - 896)*256 + tid;
        float4 v = *(const float4*)&x[idx4*4];
        __nv_bfloat16 h0,l0,h1,l1,h2,l2,h3,l3;
        split_val(v.x,h0,l0); split_val(v.y,h1,l1);
        split_val(v.z,h2,l2); split_val(v.w,h3,l3);
        __nv_bfloat162 ha; ha.x=h0; ha.y=h1;
        __nv_bfloat162 hb; hb.x=h2; hb.y=h3;
        __nv_bfloat162 la; la.x=l0; la.y=l1;
        __nv_bfloat162 lb; lb.x=l2; lb.y=l3;
        *(__nv_bfloat162*)&gA_hi[idx4*4]   = ha;
        *(__nv_bfloat162*)&gA_hi[idx4*4+2] = hb;
        *(__nv_bfloat162*)&gA_lo[idx4*4]   = la;
        *(__nv_bfloat162*)&gA_lo[idx4*4+2] = lb;
    } else if (b < 2176){
        int rel = b - 1920;
        int gw = rel*8 + (tid >> 5);
        int lane = tid & 31;
        int h = gw >> 8, c = gw & 255;
        float s = 0.f, t = 0.f;
        #pragma unroll
        for (int d = lane; d < DIM; d += 32){
            float wv = W2[(size_t)c*HD2 + h*DIM + d];
            s += wv * as2[h*DIM + d];
            t += wv * ad2[h*DIM + d];
        }
        #pragma unroll
        for (int o = 16; o > 0; o >>= 1){
            s += __shfl_down_sync(0xffffffffu, s, o);
            t += __shfl_down_sync(0xffffffffu, t, o);
        }
        if (lane == 0){ g_va_src[h*DIM + c] = s; g_va_dst[h*DIM + c] = t; }
    } else {
        // adj scan: warp per row, float4 loads (deterministic interleaved order)
        int row = (b - 2176)*8 + (tid >> 5);
        int lane = tid & 31;
        const float* arow = adj + (size_t)row * SEQ;
        int cnt = 0;
        for (int base = 0; base < SEQ; base += 128){
            float4 v = *(const float4*)&arow[base + lane*4];
            float vv[4] = {v.x, v.y, v.z, v.w};
            #pragma unroll
            for (int i = 0; i < 4; i++){
                bool p = vv[i] > 0.f;
                unsigned m = __ballot_sync(0xffffffffu, p);
                if (p){
                    int pos = cnt + __popc(m & ((1u << lane) - 1u));
                    if (pos < MAXN) g_nbr[row*MAXN + pos] = base + lane*4 + i;
                }
                cnt += __popc(m);
            }
        }
        if (lane == 0) g_cnt[row] = cnt < MAXN ? cnt : MAXN;
    }
}

// ---------------- softmax weights -------------------------------------------------
__device__ __forceinline__ void compute_weights(int row, int b, int cnt,
                                                const int* nbr, float* w, float* srcI,
                                                const float* __restrict__ srcA,
                                                const float* __restrict__ dstA){
    int tid = threadIdx.x;
    if (tid < NH) srcI[tid] = srcA[row*NH + tid];
    __syncthreads();
    for (int idx = tid; idx < cnt*NH; idx += 256){
        int n = idx >> 3, h = idx & 7;
        float e = srcI[h] + dstA[(size_t)(b*SEQ + nbr[n])*NH + h];
        w[n*NH + h] = e > 0.f ? e : 0.2f*e;
    }
    __syncthreads();
    int h = tid >> 5, lane = tid & 31;
    float m = -1e30f;
    for (int n = lane; n < cnt; n += 32) m = fmaxf(m, w[n*NH + h]);
    #pragma unroll
    for (int o = 16; o > 0; o >>= 1) m = fmaxf(m, __shfl_xor_sync(0xffffffffu, m, o));
    float ssum = 0.f;
    for (int n = lane; n < cnt; n += 32){
        float e = expf(w[n*NH + h] - m);
        w[n*NH + h] = e;
        ssum += e;
    }
    #pragma unroll
    for (int o = 16; o > 0; o >>= 1) ssum += __shfl_xor_sync(0xffffffffu, ssum, o);
    float inv = 1.f / ssum;
    for (int n = lane; n < cnt; n += 32) w[n*NH + h] *= inv;
    __syncthreads();
}

// aggregate (float4, 4-group) + residual + ELU (+optionally fused layer-2 scores)
template<bool S2>
__global__ __launch_bounds__(256)
void attn01(const float* __restrict__ resid, float* __restrict__ out){
    int row = blockIdx.x;
    int b = row / SEQ;
    int tid = threadIdx.x;
    int cnt = g_cnt[row];
    __shared__ int   nbr[MAXN];
    __shared__ float w[MAXN*NH];
    __shared__ float srcI[NH];
    __shared__ float sred[4][DIM];
    __shared__ float val[DIM];
    for (int n = tid; n < cnt; n += 256) nbr[n] = g_nbr[row*MAXN + n];
    __syncthreads();
    compute_weights(row, b, cnt, nbr, w, srcI, g_src, g_dst);

    int g4 = tid >> 6, c4 = tid & 63;
    int ch0 = c4*4;
    int hh = c4 >> 3;
    float a0 = 0.f, a1 = 0.f, a2 = 0.f, a3 = 0.f;
    float b0_ = 0.f, b1_ = 0.f, b2_ = 0.f, b3_ = 0.f;
    int n = g4;
    for (; n + 4 < cnt; n += 8){
        int j0 = nbr[n], j1 = nbr[n+4];
        float4 v0 = *(const float4*)&g_hp[((size_t)(b*SEQ + j0))*DIM + ch0];
        float4 v1 = *(const float4*)&g_hp[((size_t)(b*SEQ + j1))*DIM + ch0];
        float wt0 = w[n*NH + hh];
        float wt1 = w[(n+4)*NH + hh];
        a0 = fmaf(wt0, v0.x, a0); a1 = fmaf(wt0, v0.y, a1);
        a2 = fmaf(wt0, v0.z, a2); a3 = fmaf(wt0, v0.w, a3);
        b0_ = fmaf(wt1, v1.x, b0_); b1_ = fmaf(wt1, v1.y, b1_);
        b2_ = fmaf(wt1, v1.z, b2_); b3_ = fmaf(wt1, v1.w, b3_);
    }
    if (n < cnt){
        int j0 = nbr[n];
        float4 v0 = *(const float4*)&g_hp[((size_t)(b*SEQ + j0))*DIM + ch0];
        float wt0 = w[n*NH + hh];
        a0 = fmaf(wt0, v0.x, a0); a1 = fmaf(wt0, v0.y, a1);
        a2 = fmaf(wt0, v0.z, a2); a3 = fmaf(wt0, v0.w, a3);
    }
    a0 += b0_; a1 += b1_; a2 += b2_; a3 += b3_;
    *(float4*)&sred[g4][ch0] = make_float4(a0, a1, a2, a3);
    __syncthreads();

    int ch = tid;
    float acc = sred[0][ch] + sred[1][ch] + sred[2][ch] + sred[3][ch];
    size_t oi = (size_t)row*DIM + ch;
    float v = acc + resid[oi];
    v = v > 0.f ? v : expm1f(v);
    out[oi] = v;
    if (!S2){
        split_val(v, gA_hi[oi], gA_lo[oi]);
    } else {
        val[ch] = v;
        __syncthreads();
        int h = tid >> 5, lane = tid & 31;
        float s = 0.f, t = 0.f;
        #pragma unroll
        for (int d = lane; d < DIM; d += 32){
            float vd = val[d];
            s = fmaf(vd, g_va_src[h*DIM + d], s);
            t = fmaf(vd, g_va_dst[h*DIM + d], t);
        }
        #pragma unroll
        for (int o = 16; o > 0; o >>= 1){
            s += __shfl_down_sync(0xffffffffu, s, o);
            t += __shfl_down_sync(0xffffffffu, t, o);
        }
        if (lane == 0){ g_src2[row*NH + h] = s; g_dst2[row*NH + h] = t; }
    }
}

// layer 2: aggregate h per head — 2-group float2 gather, 16 KB smem reduce
__global__ __launch_bounds__(256)
void attn2b(){
    int row = blockIdx.x;
    int b = row / SEQ;
    int tid = threadIdx.x;
    int cnt = g_cnt[row];
    __shared__ int   nbr[MAXN];
    __shared__ float w[MAXN*NH];
    __shared__ float srcI[NH];
    __shared__ float sred[2][NH][DIM];   // 16 KB
    for (int n = tid; n < cnt; n += 256) nbr[n] = g_nbr[row*MAXN + n];
    __syncthreads();
    compute_weights(row, b, cnt, nbr, w, srcI, g_src2, g_dst2);

    int g2 = tid >> 7, c2 = tid & 127;
    int ch0 = c2*2;
    float accx[NH] = {}, accy[NH] = {};
    for (int n = g2; n < cnt; n += 2){
        int j = nbr[n];
        float2 v = *(const float2*)&g_h[(size_t)(b*SEQ + j)*DIM + ch0];
        float4 wa = *(const float4*)&w[n*NH];
        float4 wb = *(const float4*)&w[n*NH + 4];
        float ws[8] = {wa.x, wa.y, wa.z, wa.w, wb.x, wb.y, wb.z, wb.w};
        #pragma unroll
        for (int h = 0; h < NH; h++){
            accx[h] = fmaf(ws[h], v.x, accx[h]);
            accy[h] = fmaf(ws[h], v.y, accy[h]);
        }
    }
    #pragma unroll
    for (int h = 0; h < NH; h++)
        *(float2*)&sred[g2][h][ch0] = make_float2(accx[h], accy[h]);
    __syncthreads();

    int c = tid;
    #pragma unroll
    for (int h = 0; h < NH; h++){
        float s = sred[0][h][c] + sred[1][h][c];
        size_t oi = (size_t)row*HD2 + h*DIM + c;
        split_val(s, gA_hi[oi], gA_lo[oi]);
    }
}

// ---------------- LayerNorm over sum of 4 split-K partials + residual -------------
__global__ void layernorm4(const float* __restrict__ res,
                           const float* __restrict__ ln_g, const float* __restrict__ ln_b,
                           float* __restrict__ out){
    int row = blockIdx.x, tid = threadIdx.x;
    size_t oi = (size_t)row*DIM + tid;
    float v = g_part[oi] + g_part[oi + (size_t)ROWS*DIM]
            + g_part[oi + 2*(size_t)ROWS*DIM] + g_part[oi + 3*(size_t)ROWS*DIM]
            + res[oi];
    __shared__ float red[8];
    __shared__ float mu, rstd;
    float s = v;
    #pragma unroll
    for (int o = 16; o > 0; o >>= 1) s += __shfl_xor_sync(0xffffffffu, s, o);
    if ((tid & 31) == 0) red[tid >> 5] = s;
    __syncthreads();
    if (tid == 0){ float t = 0.f; for (int i = 0; i < 8; i++) t += red[i]; mu = t / 256.f; }
    __syncthreads();
    float d = v - mu;
    s = d*d;
    #pragma unroll
    for (int o = 16; o > 0; o >>= 1) s += __shfl_xor_sync(0xffffffffu, s, o);
    if ((tid & 31) == 0) red[tid >> 5] = s;
    __syncthreads();
    if (tid == 0){ float t = 0.f; for (int i = 0; i < 8; i++) t += red[i]; rstd = rsqrtf(t/256.f + 1e-5f); }
    __syncthreads();
    float o = d*rstd*ln_g[tid] + ln_b[tid];
    out[oi] = o;
    split_val(o, gA_hi[oi], gA_lo[oi]);
}

// ---------------- launch ---------------------------------------------------------
extern "C" void kernel_launch(void* const* d_in, const int* in_sizes, int n_in,
                              void* d_out, int out_size){
    const float* adj    = (const float*)d_in[0];
    const float* x      = (const float*)d_in[1];
    const float* W0     = (const float*)d_in[2];
    const float* a_src0 = (const float*)d_in[3];
    const float* a_dst0 = (const float*)d_in[4];
    const float* W1     = (const float*)d_in[5];
    const float* a_src1 = (const float*)d_in[6];
    const float* a_dst1 = (const float*)d_in[7];
    const float* W2     = (const float*)d_in[8];
    const float* a_src2 = (const float*)d_in[9];
    const float* a_dst2 = (const float*)d_in[10];
    const float* ln_g   = (const float*)d_in[11];
    const float* ln_b   = (const float*)d_in[12];
    const float* ff_w1  = (const float*)d_in[13];
    const float* ff_b1  = (const float*)d_in[14];
    const float* ff_w2  = (const float*)d_in[15];
    const float* ff_b2  = (const float*)d_in[16];
    float* out = (float*)d_out;

    float *p_hp, *p_h, *p_ln, *p_part;
    __nv_bfloat16 *pAh, *pAl, *pFh, *pFl;
    __nv_bfloat16 *pw0h,*pw0l,*pw1h,*pw1l,*pw2h,*pw2l,*pf1h,*pf1l,*pf2h,*pf2l;
    cudaGetSymbolAddress((void**)&p_hp,  g_hp);
    cudaGetSymbolAddress((void**)&p_h,   g_h);
    cudaGetSymbolAddress((void**)&p_ln,  g_ln);
    cudaGetSymbolAddress((void**)&p_part, g_part);
    cudaGetSymbolAddress((void**)&pAh, gA_hi);  cudaGetSymbolAddress((void**)&pAl, gA_lo);
    cudaGetSymbolAddress((void**)&pFh, gF_hi);  cudaGetSymbolAddress((void**)&pFl, gF_lo);
    cudaGetSymbolAddress((void**)&pw0h, w0_hi); cudaGetSymbolAddress((void**)&pw0l, w0_lo);
    cudaGetSymbolAddress((void**)&pw1h, w1_hi); cudaGetSymbolAddress((void**)&pw1l, w1_lo);
    cudaGetSymbolAddress((void**)&pw2h, w2_hi); cudaGetSymbolAddress((void**)&pw2l, w2_lo);
    cudaGetSymbolAddress((void**)&pf1h, f1_hi); cudaGetSymbolAddress((void**)&pf1l, f1_lo);
    cudaGetSymbolAddress((void**)&pf2h, f2_hi); cudaGetSymbolAddress((void**)&pf2l, f2_lo);

    const int SM64  = 3*(2*128*40*2 + 2*64*40*2);    // 92160
    cudaFuncSetAttribute(gemm_mma<4,64>, cudaFuncAttributeMaxDynamicSharedMemorySize, SM64);
    cudaFuncSetAttribute(gemm_mma<0,64>, cudaFuncAttributeMaxDynamicSharedMemorySize, SM64);
    cudaFuncSetAttribute(gemm_mma<2,64>, cudaFuncAttributeMaxDynamicSharedMemorySize, SM64);
    cudaFuncSetAttribute(gemm_mma<1,64>, cudaFuncAttributeMaxDynamicSharedMemorySize, SM64);

    dim3 blk(256);
    prep<<<2688, blk>>>(W0, W1, W2, ff_w1, ff_w2, x, a_src2, a_dst2, adj);

    // ---- GAT layer 0 (GEMM + fused scores) ----
    gemm_mma<4,64><<<dim3(4,32), blk, SM64>>>(pAh, pAl, pw0h, pw0l, nullptr, nullptr,
                                              a_src0, a_dst0, p_hp, nullptr, nullptr, ROWS, DIM, DIM, DIM);
    attn01<false><<<ROWS, blk>>>(x, p_h);

    // ---- GAT layer 1 (GEMM + fused scores; attn also emits layer-2 scores) ----
    gemm_mma<4,64><<<dim3(4,32), blk, SM64>>>(pAh, pAl, pw1h, pw1l, nullptr, nullptr,
                                              a_src1, a_dst1, p_hp, nullptr, nullptr, ROWS, DIM, DIM, DIM);
    attn01<true><<<ROWS, blk>>>(p_h, p_h);

    // ---- GAT layer 2: aggregate, then split-K x4 GEMM ----
    attn2b<<<ROWS, blk>>>();
    gemm_mma<0,64><<<dim3(4,32,4), blk, SM64>>>(pAh, pAl, pw2h, pw2l, nullptr, nullptr,
                                                nullptr, nullptr, p_part, nullptr, nullptr,
                                                ROWS, DIM, HD2, 512);

    // ---- LayerNorm (fused partial-reduce + residual) ----
    layernorm4<<<ROWS, blk>>>(p_h, ln_g, ln_b, p_ln);

    // ---- FFN ----
    gemm_mma<1,64><<<dim3(8,32), blk, SM64>>>(pAh, pAl, pf1h, pf1l, ff_b1, nullptr,
                                              nullptr, nullptr, nullptr, pFh, pFl, ROWS, FFH, DIM, DIM);
    gemm_mma<2,64><<<dim3(4,32), blk, SM64>>>(pFh, pFl, pf2h, pf2l, ff_b2, p_ln,
                                              nullptr, nullptr, out, nullptr, nullptr, ROWS, DIM, FFH, FFH);
}